// round 7
// baseline (speedup 1.0000x reference)
#include <cuda_runtime.h>
#include <cstdint>

// Shape: inp:[2048,2048,3] f32, w_ih:[96,3], w_hh:[96,32], bias:[96], bias_n:[32]
// out:[2048,2048,1] f32 (h[0] each step)
#define TT 2048
#define BB 2048
#define CH 2          // independent sequences (chains) per warp

__device__ __forceinline__ void ffma2(unsigned long long &d,
                                      unsigned long long a,
                                      unsigned long long b) {
    asm("fma.rn.f32x2 %0, %1, %2, %0;" : "+l"(d) : "l"(a), "l"(b));
}

__device__ __forceinline__ float2 unpack2(unsigned long long v) {
    float2 r;
    asm("mov.b64 {%0, %1}, %2;" : "=f"(r.x), "=f"(r.y) : "l"(v));
    return r;
}

__device__ __forceinline__ float tanh_hw(float x) {
    float y;
    asm("tanh.approx.f32 %0, %1;" : "=f"(y) : "f"(x));
    return y;
}
__device__ __forceinline__ float sigmoid_hw(float x) {
    return fmaf(0.5f, tanh_hw(0.5f * x), 0.5f);
}

// One warp per block, TWO sequences per warp. Lane j owns hidden unit j of
// both chains; W_hh register tiles (48 packed f32x2) are SHARED between the
// chains, so the second chain costs only its state/accumulators. The two
// dependency chains interleave, doubling per-warp ILP (this kernel is
// latency-bound, not issue-bound). One __syncwarp per step covers both.
__global__ void __launch_bounds__(32, 8)
gru_warp_kernel(const float* __restrict__ inp,
                const float* __restrict__ w_ih,
                const float* __restrict__ w_hh,
                const float* __restrict__ bias,
                const float* __restrict__ bias_n,
                float* __restrict__ out) {
    __shared__ __align__(16) float hbuf[CH][2][32];
    __shared__ float xbuf[CH][96];   // 32 timesteps of x per chain

    const int j = threadIdx.x;       // hidden unit 0..31

    // ---- shared-across-chains weights into registers (one-time) ----
    unsigned long long wr[16], wz[16], wa[16];
    {
        const unsigned long long* rr =
            reinterpret_cast<const unsigned long long*>(w_hh + (0 * 32 + j) * 32);
        const unsigned long long* rz =
            reinterpret_cast<const unsigned long long*>(w_hh + (1 * 32 + j) * 32);
        const unsigned long long* ra =
            reinterpret_cast<const unsigned long long*>(w_hh + (2 * 32 + j) * 32);
#pragma unroll
        for (int k = 0; k < 16; k++) { wr[k] = rr[k]; wz[k] = rz[k]; wa[k] = ra[k]; }
    }
    const float wir0 = w_ih[(0 * 32 + j) * 3 + 0];
    const float wir1 = w_ih[(0 * 32 + j) * 3 + 1];
    const float wir2 = w_ih[(0 * 32 + j) * 3 + 2];
    const float wiz0 = w_ih[(1 * 32 + j) * 3 + 0];
    const float wiz1 = w_ih[(1 * 32 + j) * 3 + 1];
    const float wiz2 = w_ih[(1 * 32 + j) * 3 + 2];
    const float wia0 = w_ih[(2 * 32 + j) * 3 + 0];
    const float wia1 = w_ih[(2 * 32 + j) * 3 + 1];
    const float wia2 = w_ih[(2 * 32 + j) * 3 + 2];
    const float br  = bias[0 * 32 + j];
    const float bz  = bias[1 * 32 + j];
    const float ban = bias[2 * 32 + j] + bias_n[j];

    const float* gx[CH];
    float*       gout[CH];
    float        h[CH];
    float        p0[CH], p1[CH], p2[CH];
#pragma unroll
    for (int c = 0; c < CH; c++) {
        const int b = blockIdx.x * CH + c;
        gx[c]   = inp + (size_t)b * (TT * 3);
        gout[c] = out + (size_t)b * TT;
        h[c] = 0.0f;
        p0[c] = gx[c][j];
        p1[c] = gx[c][32 + j];
        p2[c] = gx[c][64 + j];
    }

    for (int t = 0; t < TT; t++) {
        if ((t & 31) == 0) {
            __syncwarp();            // previous chunk's xbuf readers done
            const int nb = (t + 32) * 3;
#pragma unroll
            for (int c = 0; c < CH; c++) {
                xbuf[c][j]      = p0[c];
                xbuf[c][32 + j] = p1[c];
                xbuf[c][64 + j] = p2[c];
                if (nb < TT * 3) {   // prefetch next chunk; hidden over 32 steps
                    p0[c] = gx[c][nb + j];
                    p1[c] = gx[c][nb + 32 + j];
                    p2[c] = gx[c][nb + 64 + j];
                }
            }
        }

        const int par = t & 1;
        hbuf[0][par][j] = h[0];
        hbuf[1][par][j] = h[1];
        __syncwarp();

        const int ti = (t & 31) * 3;
        float ir[CH], iz[CH], ia[CH];
#pragma unroll
        for (int c = 0; c < CH; c++) {
            const float x0 = xbuf[c][ti + 0];
            const float x1 = xbuf[c][ti + 1];
            const float x2 = xbuf[c][ti + 2];
            ir[c] = fmaf(wir2, x2, fmaf(wir1, x1, fmaf(wir0, x0, br)));
            iz[c] = fmaf(wiz2, x2, fmaf(wiz1, x1, fmaf(wiz0, x0, bz)));
            ia[c] = fmaf(wia2, x2, fmaf(wia1, x1, fmaf(wia0, x0, ban)));
        }

        // Interleaved hidden matvecs: 2 chains x 48 dual-FMAs, shared weights.
        unsigned long long accr[CH], accz[CH], acca[CH];
#pragma unroll
        for (int c = 0; c < CH; c++) { accr[c] = 0ull; accz[c] = 0ull; acca[c] = 0ull; }
        const ulonglong2* hp0 = reinterpret_cast<const ulonglong2*>(hbuf[0][par]);
        const ulonglong2* hp1 = reinterpret_cast<const ulonglong2*>(hbuf[1][par]);
#pragma unroll
        for (int q = 0; q < 8; q++) {
            const ulonglong2 a0 = hp0[q];
            const ulonglong2 a1 = hp1[q];
            ffma2(accr[0], wr[2 * q],     a0.x);
            ffma2(accr[1], wr[2 * q],     a1.x);
            ffma2(accz[0], wz[2 * q],     a0.x);
            ffma2(accz[1], wz[2 * q],     a1.x);
            ffma2(acca[0], wa[2 * q],     a0.x);
            ffma2(acca[1], wa[2 * q],     a1.x);
            ffma2(accr[0], wr[2 * q + 1], a0.y);
            ffma2(accr[1], wr[2 * q + 1], a1.y);
            ffma2(accz[0], wz[2 * q + 1], a0.y);
            ffma2(accz[1], wz[2 * q + 1], a1.y);
            ffma2(acca[0], wa[2 * q + 1], a0.y);
            ffma2(acca[1], wa[2 * q + 1], a1.y);
        }

#pragma unroll
        for (int c = 0; c < CH; c++) {
            const float2 fr = unpack2(accr[c]);
            const float2 fz = unpack2(accz[c]);
            const float2 fa = unpack2(acca[c]);
            const float r = sigmoid_hw(ir[c] + (fr.x + fr.y));
            const float z = sigmoid_hw(iz[c] + (fz.x + fz.y));
            const float n = tanh_hw(fmaf(r, fa.x + fa.y, ia[c]));
            h[c] = fmaf(z, h[c] - n, n);      // (1-z)*n + z*h
            if (j == 0) gout[c][t] = h[c];
        }
    }
}

extern "C" void kernel_launch(void* const* d_in, const int* in_sizes, int n_in,
                              void* d_out, int out_size) {
    const float* inp    = (const float*)d_in[0];
    const float* w_ih   = (const float*)d_in[1];
    const float* w_hh   = (const float*)d_in[2];
    const float* bias   = (const float*)d_in[3];
    const float* bias_n = (const float*)d_in[4];
    float* out = (float*)d_out;
    gru_warp_kernel<<<BB / CH, 32>>>(inp, w_ih, w_hh, bias, bias_n, out);
}